// round 1
// baseline (speedup 1.0000x reference)
#include <cuda_runtime.h>

// Problem constants
#define B_  2
#define H_  12
#define S_  2048
#define D_  64
#define BR  32      // query tile rows
#define BC  32      // key tile rows
#define DS  68      // padded row stride in smem (floats) to avoid bank conflicts
#define NTHREADS 256

// Scratch: first index of each query's segment (block_ids are sorted per batch)
__device__ int g_seg_start[B_ * S_];

__global__ void segstart_kernel(const int* __restrict__ block_ids) {
    int idx = blockIdx.x * blockDim.x + threadIdx.x;
    if (idx >= B_ * S_) return;
    int b = idx / S_, qpos = idx % S_;
    const int* bi = block_ids + b * S_;
    int val = bi[qpos];
    int lo = 0, hi = qpos;
    while (lo < hi) {
        int mid = (lo + hi) >> 1;
        if (bi[mid] < val) lo = mid + 1; else hi = mid;
    }
    g_seg_start[idx] = lo;
}

__global__ __launch_bounds__(NTHREADS, 2)
void attn_kernel(const float* __restrict__ Q, const float* __restrict__ K,
                 const float* __restrict__ V, float* __restrict__ O) {
    __shared__ float Qs[BR][DS];
    __shared__ float Ks[BC][DS];
    __shared__ float Vs[BC][DS];
    __shared__ float Ps[BR][BC + 1];

    const int qt = blockIdx.x, h = blockIdx.y, b = blockIdx.z;
    const int q0 = qt * BR;
    const long base = ((long)(b * H_ + h)) * S_ * D_;
    const float* Qb = Q + base;
    const float* Kb = K + base;
    const float* Vb = V + base;

    const int t = threadIdx.x;

    // Load Q tile (32 x 64 floats) with float4
    for (int i = t; i < BR * (D_ / 4); i += NTHREADS) {
        int r = i >> 4, c4 = i & 15;
        *(float4*)&Qs[r][c4 * 4] = *(const float4*)&Qb[(long)(q0 + r) * D_ + c4 * 4];
    }

    // Thread mapping: row r = t/8 (8 threads per row), col group g = t%8.
    // Score cols owned: c0..c0+3. Output dims owned: g*8..g*8+7.
    const int r  = t >> 3;
    const int g  = t & 7;
    const int c0 = g * 4;
    const int rg = q0 + r;
    const int my_start = g_seg_start[b * S_ + rg];
    // seg_start is nondecreasing -> row q0 has the smallest start in this tile
    const int kstart = (g_seg_start[b * S_ + q0] / BC) * BC;

    // Ghost logit: acts like an extra key with score 0, value 0 -> init m=0, l=1.
    float m = 0.f, l = 1.f;
    float acc[8];
    #pragma unroll
    for (int j = 0; j < 8; j++) acc[j] = 0.f;

    const float scaling = 0.125f;  // 1/sqrt(64)

    for (int kt = kstart; kt <= q0; kt += BC) {
        __syncthreads();  // protect K/V/P from previous iteration's readers
        for (int i = t; i < BC * (D_ / 4); i += NTHREADS) {
            int rr = i >> 4, c4 = i & 15;
            *(float4*)&Ks[rr][c4 * 4] = *(const float4*)&Kb[(long)(kt + rr) * D_ + c4 * 4];
            *(float4*)&Vs[rr][c4 * 4] = *(const float4*)&Vb[(long)(kt + rr) * D_ + c4 * 4];
        }
        __syncthreads();

        // Scores: s[cc] = dot(Q[r], K[c0+cc]) over D=64
        float s0 = 0.f, s1 = 0.f, s2 = 0.f, s3 = 0.f;
        #pragma unroll
        for (int d4 = 0; d4 < 16; d4++) {
            float4 qv = *(float4*)&Qs[r][d4 * 4];
            float4 k0 = *(float4*)&Ks[c0 + 0][d4 * 4];
            float4 k1 = *(float4*)&Ks[c0 + 1][d4 * 4];
            float4 k2 = *(float4*)&Ks[c0 + 2][d4 * 4];
            float4 k3 = *(float4*)&Ks[c0 + 3][d4 * 4];
            s0 += qv.x * k0.x; s0 += qv.y * k0.y; s0 += qv.z * k0.z; s0 += qv.w * k0.w;
            s1 += qv.x * k1.x; s1 += qv.y * k1.y; s1 += qv.z * k1.z; s1 += qv.w * k1.w;
            s2 += qv.x * k2.x; s2 += qv.y * k2.y; s2 += qv.z * k2.z; s2 += qv.w * k2.w;
            s3 += qv.x * k3.x; s3 += qv.y * k3.y; s3 += qv.z * k3.z; s3 += qv.w * k3.w;
        }
        float sc[4] = {s0 * scaling, s1 * scaling, s2 * scaling, s3 * scaling};

        // Mask: same segment AND causal. Hard mask -> exp underflows to exact 0.
        #pragma unroll
        for (int cc = 0; cc < 4; cc++) {
            int cg = kt + c0 + cc;
            if (cg < my_start || cg > rg) sc[cc] = -1e30f;
        }

        // Row max across the 8 threads owning this row (contiguous 8-lane group)
        float mt = fmaxf(fmaxf(sc[0], sc[1]), fmaxf(sc[2], sc[3]));
        #pragma unroll
        for (int off = 1; off < 8; off <<= 1)
            mt = fmaxf(mt, __shfl_xor_sync(0xffffffffu, mt, off));

        float m_new = fmaxf(m, mt);
        float corr = __expf(m - m_new);
        float p[4];
        float lsum = 0.f;
        #pragma unroll
        for (int cc = 0; cc < 4; cc++) { p[cc] = __expf(sc[cc] - m_new); lsum += p[cc]; }
        #pragma unroll
        for (int off = 1; off < 8; off <<= 1)
            lsum += __shfl_xor_sync(0xffffffffu, lsum, off);
        l = l * corr + lsum;
        m = m_new;

        #pragma unroll
        for (int cc = 0; cc < 4; cc++) Ps[r][c0 + cc] = p[cc];
        #pragma unroll
        for (int j = 0; j < 8; j++) acc[j] *= corr;
        __syncthreads();

        // PV: acc[j] += sum_c Ps[r][c] * Vs[c][g*8 + j]
        #pragma unroll 8
        for (int c = 0; c < BC; c++) {
            float pv = Ps[r][c];
            float4 v0 = *(float4*)&Vs[c][g * 8];
            float4 v1 = *(float4*)&Vs[c][g * 8 + 4];
            acc[0] += pv * v0.x; acc[1] += pv * v0.y;
            acc[2] += pv * v0.z; acc[3] += pv * v0.w;
            acc[4] += pv * v1.x; acc[5] += pv * v1.y;
            acc[6] += pv * v1.z; acc[7] += pv * v1.w;
        }
    }

    float inv = 1.f / l;
    float* op = O + base + (long)rg * D_ + g * 8;
    float4 o0 = make_float4(acc[0] * inv, acc[1] * inv, acc[2] * inv, acc[3] * inv);
    float4 o1 = make_float4(acc[4] * inv, acc[5] * inv, acc[6] * inv, acc[7] * inv);
    *(float4*)&op[0] = o0;
    *(float4*)&op[4] = o1;
}

extern "C" void kernel_launch(void* const* d_in, const int* in_sizes, int n_in,
                              void* d_out, int out_size) {
    const float* q   = (const float*)d_in[0];
    const float* k   = (const float*)d_in[1];
    const float* v   = (const float*)d_in[2];
    const int* bids  = (const int*)d_in[3];
    float* out       = (float*)d_out;

    segstart_kernel<<<(B_ * S_ + 255) / 256, 256>>>(bids);

    dim3 grid(S_ / BR, H_, B_);
    attn_kernel<<<grid, NTHREADS>>>(q, k, v, out);
}

// round 2
// speedup vs baseline: 4.6574x; 4.6574x over previous
#include <cuda_runtime.h>

#define B_  2
#define H_  12
#define S_  2048
#define D_  64
#define BR  64
#define BC  64
#define NT  256
#define STRIDE 68   // padded row stride (floats)

typedef unsigned long long ull;

__device__ int g_seg_start[B_ * S_];

__global__ void segstart_kernel(const int* __restrict__ block_ids) {
    int idx = blockIdx.x * blockDim.x + threadIdx.x;
    if (idx >= B_ * S_) return;
    int b = idx / S_, qpos = idx % S_;
    const int* bi = block_ids + b * S_;
    int val = bi[qpos];
    int lo = 0, hi = qpos;
    while (lo < hi) {
        int mid = (lo + hi) >> 1;
        if (bi[mid] < val) lo = mid + 1; else hi = mid;
    }
    g_seg_start[idx] = lo;
}

__device__ __forceinline__ ull fma2(ull a, ull b, ull c) {
    ull d;
    asm("fma.rn.f32x2 %0, %1, %2, %3;" : "=l"(d) : "l"(a), "l"(b), "l"(c));
    return d;
}
__device__ __forceinline__ ull mul2(ull a, ull b) {
    ull d;
    asm("mul.rn.f32x2 %0, %1, %2;" : "=l"(d) : "l"(a), "l"(b));
    return d;
}
__device__ __forceinline__ ull pack2(float lo, float hi) {
    ull d;
    asm("mov.b64 %0, {%1, %2};" : "=l"(d) : "f"(lo), "f"(hi));
    return d;
}
__device__ __forceinline__ float2 unpack2(ull v) {
    float2 r;
    asm("mov.b64 {%0, %1}, %2;" : "=f"(r.x), "=f"(r.y) : "l"(v));
    return r;
}

extern __shared__ float smem[];

__global__ __launch_bounds__(NT, 2)
void attn_kernel(const float* __restrict__ Q, const float* __restrict__ K,
                 const float* __restrict__ V, float* __restrict__ O) {
    float* Qs = smem;                       // [BR][STRIDE] row-major
    float* Ks = Qs + BR * STRIDE;           // [BC][STRIDE] row-major
    float* Vs = Ks + BC * STRIDE;           // [BC][STRIDE] dim-permuted cols
    float* Ps = Vs + BC * STRIDE;           // [BC][STRIDE] row-permuted cols

    const int qt = blockIdx.x, h = blockIdx.y, b = blockIdx.z;
    const int q0 = qt * BR;
    const long base = ((long)(b * H_ + h)) * S_ * D_;
    const float* Qb = Q + base + (long)q0 * D_;
    const float* Kb = K + base;
    const float* Vb = V + base;

    const int t  = threadIdx.x;
    const int tx = t & 15;       // col/dim group: owns cols tx+16j
    const int ty = t >> 4;       // row group: owns rows ty+16i

    // Load Q tile (64 x 64 floats), 4 float4 per thread
    #pragma unroll
    for (int u = 0; u < 4; u++) {
        int idx = t + NT * u;
        int r = idx >> 4, c4 = idx & 15;
        *(float4*)&Qs[r * STRIDE + c4 * 4] = *(const float4*)&Qb[r * D_ + c4 * 4];
    }

    int st[4];
    #pragma unroll
    for (int i = 0; i < 4; i++) st[i] = g_seg_start[b * S_ + q0 + ty + 16 * i];
    const int kstart = (g_seg_start[b * S_ + q0] / BC) * BC;

    // Ghost logit == extra key with score 0, value 0 -> init m=0, l=1
    float m[4] = {0.f, 0.f, 0.f, 0.f};
    float l[4] = {1.f, 1.f, 1.f, 1.f};
    ull oacc[4][2];   // [row i][dim-pair jj]; lo=dim tx+32jj, hi=dim tx+16+32jj
    #pragma unroll
    for (int i = 0; i < 4; i++) { oacc[i][0] = 0ull; oacc[i][1] = 0ull; }

    const float scaling = 0.125f;

    for (int kt = kstart; kt <= q0; kt += BC) {
        __syncthreads();   // previous iteration's PV readers done

        // Load K (row-major) and V (dim-permuted: dim d -> col (d&15)*4 + (d>>4))
        #pragma unroll
        for (int u = 0; u < 4; u++) {
            int idx = t + NT * u;
            int r = idx >> 4, c4 = idx & 15;
            *(float4*)&Ks[r * STRIDE + c4 * 4] =
                *(const float4*)&Kb[(long)(kt + r) * D_ + c4 * 4];
            float4 vv = *(const float4*)&Vb[(long)(kt + r) * D_ + c4 * 4];
            int d0 = c4 * 4;
            Vs[r * STRIDE + ((d0 + 0) & 15) * 4 + ((d0 + 0) >> 4)] = vv.x;
            Vs[r * STRIDE + ((d0 + 1) & 15) * 4 + ((d0 + 1) >> 4)] = vv.y;
            Vs[r * STRIDE + ((d0 + 2) & 15) * 4 + ((d0 + 2) >> 4)] = vv.z;
            Vs[r * STRIDE + ((d0 + 3) & 15) * 4 + ((d0 + 3) >> 4)] = vv.w;
        }
        __syncthreads();

        // ---- QK: 4x4 fragment, packed f32x2 accumulation over k ----
        ull acc[4][4];
        #pragma unroll
        for (int i = 0; i < 4; i++)
            #pragma unroll
            for (int j = 0; j < 4; j++) acc[i][j] = 0ull;

        #pragma unroll 4
        for (int d4 = 0; d4 < 16; d4++) {
            ulonglong2 qp[4];
            #pragma unroll
            for (int i = 0; i < 4; i++)
                qp[i] = *(ulonglong2*)&Qs[(ty + 16 * i) * STRIDE + d4 * 4];
            #pragma unroll
            for (int j = 0; j < 4; j++) {
                ulonglong2 kp = *(ulonglong2*)&Ks[(tx + 16 * j) * STRIDE + d4 * 4];
                #pragma unroll
                for (int i = 0; i < 4; i++) {
                    acc[i][j] = fma2(qp[i].x, kp.x, acc[i][j]);
                    acc[i][j] = fma2(qp[i].y, kp.y, acc[i][j]);
                }
            }
        }

        // reduce pairs, scale, mask
        float sc[4][4];
        #pragma unroll
        for (int i = 0; i < 4; i++) {
            int rg = q0 + ty + 16 * i;
            #pragma unroll
            for (int j = 0; j < 4; j++) {
                float2 f = unpack2(acc[i][j]);
                float s = (f.x + f.y) * scaling;
                int cg = kt + tx + 16 * j;
                sc[i][j] = (cg < st[i] || cg > rg) ? -1e30f : s;
            }
        }

        // ---- online softmax (row spread over 16 lanes of a half-warp) ----
        float pr[4][4];
        #pragma unroll
        for (int i = 0; i < 4; i++) {
            float mt = fmaxf(fmaxf(sc[i][0], sc[i][1]), fmaxf(sc[i][2], sc[i][3]));
            #pragma unroll
            for (int off = 1; off < 16; off <<= 1)
                mt = fmaxf(mt, __shfl_xor_sync(0xffffffffu, mt, off));
            float mn = fmaxf(m[i], mt);
            float corr = __expf(m[i] - mn);
            float ls = 0.f;
            #pragma unroll
            for (int j = 0; j < 4; j++) {
                pr[i][j] = __expf(sc[i][j] - mn);
                ls += pr[i][j];
            }
            #pragma unroll
            for (int off = 1; off < 16; off <<= 1)
                ls += __shfl_xor_sync(0xffffffffu, ls, off);
            l[i] = l[i] * corr + ls;
            m[i] = mn;
            ull c2 = pack2(corr, corr);
            oacc[i][0] = mul2(oacc[i][0], c2);
            oacc[i][1] = mul2(oacc[i][1], c2);
        }

        // store P row-permuted: P[col][perm(row)] with perm(ty+16i)=ty*4+i
        #pragma unroll
        for (int j = 0; j < 4; j++) {
            float4 w = make_float4(pr[0][j], pr[1][j], pr[2][j], pr[3][j]);
            *(float4*)&Ps[(tx + 16 * j) * STRIDE + ty * 4] = w;
        }
        __syncthreads();

        // ---- PV: per key, 2 LDS.128 + 8 FFMA2 ----
        #pragma unroll 8
        for (int k = 0; k < BC; k++) {
            float4 pf = *(float4*)&Ps[k * STRIDE + ty * 4];
            ulonglong2 vf = *(ulonglong2*)&Vs[k * STRIDE + tx * 4];
            ull pb0 = pack2(pf.x, pf.x);
            ull pb1 = pack2(pf.y, pf.y);
            ull pb2 = pack2(pf.z, pf.z);
            ull pb3 = pack2(pf.w, pf.w);
            oacc[0][0] = fma2(pb0, vf.x, oacc[0][0]);
            oacc[0][1] = fma2(pb0, vf.y, oacc[0][1]);
            oacc[1][0] = fma2(pb1, vf.x, oacc[1][0]);
            oacc[1][1] = fma2(pb1, vf.y, oacc[1][1]);
            oacc[2][0] = fma2(pb2, vf.x, oacc[2][0]);
            oacc[2][1] = fma2(pb2, vf.y, oacc[2][1]);
            oacc[3][0] = fma2(pb3, vf.x, oacc[3][0]);
            oacc[3][1] = fma2(pb3, vf.y, oacc[3][1]);
        }
    }

    // epilogue: Vs pack mapping -> vf.x = dims (tx, tx+16), vf.y = (tx+32, tx+48)
    #pragma unroll
    for (int i = 0; i < 4; i++) {
        float inv = 1.f / l[i];
        int row = q0 + ty + 16 * i;
        float* op = (float*)O + base + (long)row * D_;
        float2 o0 = unpack2(oacc[i][0]);
        float2 o1 = unpack2(oacc[i][1]);
        op[tx]      = o0.x * inv;
        op[tx + 16] = o0.y * inv;
        op[tx + 32] = o1.x * inv;
        op[tx + 48] = o1.y * inv;
    }
}

extern "C" void kernel_launch(void* const* d_in, const int* in_sizes, int n_in,
                              void* d_out, int out_size) {
    const float* q  = (const float*)d_in[0];
    const float* k  = (const float*)d_in[1];
    const float* v  = (const float*)d_in[2];
    const int* bids = (const int*)d_in[3];
    float* out      = (float*)d_out;

    segstart_kernel<<<(B_ * S_ + 255) / 256, 256>>>(bids);

    const int smem_bytes = 4 * BC * STRIDE * sizeof(float);  // 69632
    cudaFuncSetAttribute(attn_kernel, cudaFuncAttributeMaxDynamicSharedMemorySize,
                         smem_bytes);
    dim3 grid(S_ / BR, H_, B_);
    attn_kernel<<<grid, NT, smem_bytes>>>(q, k, v, out);
}